// round 3
// baseline (speedup 1.0000x reference)
#include <cuda_runtime.h>
#include <cstdint>

// ============================================================
// MultiHeadAttention: B=4, T=2048, E=1024, H=16, D=64
// tf32 mma.sync end-to-end (fp32 accumulate)
// ============================================================

#define DINL __device__ __forceinline__

DINL float f2tf(float x) {
    unsigned u;
    asm("cvt.rna.tf32.f32 %0, %1;" : "=r"(u) : "f"(x));
    return __uint_as_float(u);
}
DINL unsigned fau(float x) { return __float_as_uint(x); }

DINL void mma_tf32(float& c0, float& c1, float& c2, float& c3,
                   unsigned a0, unsigned a1, unsigned a2, unsigned a3,
                   unsigned b0, unsigned b1) {
    asm volatile(
        "mma.sync.aligned.m16n8k8.row.col.f32.tf32.tf32.f32 "
        "{%0,%1,%2,%3}, {%4,%5,%6,%7}, {%8,%9}, {%0,%1,%2,%3};\n"
        : "+f"(c0), "+f"(c1), "+f"(c2), "+f"(c3)
        : "r"(a0), "r"(a1), "r"(a2), "r"(a3), "r"(b0), "r"(b1));
}

// Scratch: Q/K/V in [B*H, T, D] layout, attention out in [B*T, E]
__device__ float g_q[8388608];
__device__ float g_k[8388608];
__device__ float g_v[8388608];
__device__ float g_ao[8388608];

// ------------------------------------------------------------
// GEMM: C = (A[M,1024] @ W[1024,1024]^T + bias) * scale
// Block tile 128x128, K-tile 32, 256 threads (8 warps: 2x4, warp tile 64x32)
// qkv_mode=1: write C[m,n] -> out[((b*16+h)*2048+t)*64+d], m=b*2048+t, n=h*64+d
// qkv_mode=0: row-major C[m*1024+n]
// ------------------------------------------------------------
__global__ __launch_bounds__(256) void gemm_tf32_kernel(
    const float* __restrict__ A, const float* __restrict__ W,
    const float* __restrict__ bias, float* __restrict__ C,
    float scale, int qkv_mode)
{
    __shared__ float As[128][36];
    __shared__ float Bs[128][36];

    const int tid  = threadIdx.x;
    const int lane = tid & 31;
    const int warp = tid >> 5;
    const int wm = (warp >> 2) * 64;   // warp M offset (0 or 64)
    const int wn = (warp & 3) * 32;    // warp N offset
    const int bM = blockIdx.y * 128;
    const int bN = blockIdx.x * 128;
    const int rA = lane >> 2;          // 0..7
    const int t4 = lane & 3;           // 0..3

    float acc[4][4][4];
#pragma unroll
    for (int i = 0; i < 4; i++)
#pragma unroll
        for (int j = 0; j < 4; j++)
#pragma unroll
            for (int e = 0; e < 4; e++) acc[i][j][e] = 0.f;

    const int lrow = tid >> 3;          // 0..31
    const int lcol = (tid & 7) * 4;     // 0..28

    for (int kt = 0; kt < 1024; kt += 32) {
#pragma unroll
        for (int r = 0; r < 4; r++) {
            int row = lrow + 32 * r;
            float4 a4 = *(const float4*)(A + (long)(bM + row) * 1024 + kt + lcol);
            float4 b4 = *(const float4*)(W + (long)(bN + row) * 1024 + kt + lcol);
            float4 ac = make_float4(f2tf(a4.x), f2tf(a4.y), f2tf(a4.z), f2tf(a4.w));
            float4 bc = make_float4(f2tf(b4.x), f2tf(b4.y), f2tf(b4.z), f2tf(b4.w));
            *(float4*)&As[row][lcol] = ac;
            *(float4*)&Bs[row][lcol] = bc;
        }
        __syncthreads();

#pragma unroll
        for (int kk = 0; kk < 32; kk += 8) {
            unsigned af[4][4], bf[4][2];
#pragma unroll
            for (int mi = 0; mi < 4; mi++) {
                int r0 = wm + 16 * mi + rA;
                af[mi][0] = fau(As[r0][kk + t4]);
                af[mi][1] = fau(As[r0 + 8][kk + t4]);
                af[mi][2] = fau(As[r0][kk + 4 + t4]);
                af[mi][3] = fau(As[r0 + 8][kk + 4 + t4]);
            }
#pragma unroll
            for (int nj = 0; nj < 4; nj++) {
                int c0 = wn + 8 * nj + rA;
                bf[nj][0] = fau(Bs[c0][kk + t4]);
                bf[nj][1] = fau(Bs[c0][kk + 4 + t4]);
            }
#pragma unroll
            for (int mi = 0; mi < 4; mi++)
#pragma unroll
                for (int nj = 0; nj < 4; nj++)
                    mma_tf32(acc[mi][nj][0], acc[mi][nj][1], acc[mi][nj][2], acc[mi][nj][3],
                             af[mi][0], af[mi][1], af[mi][2], af[mi][3],
                             bf[nj][0], bf[nj][1]);
        }
        __syncthreads();
    }

    // epilogue
#pragma unroll
    for (int mi = 0; mi < 4; mi++) {
#pragma unroll
        for (int nj = 0; nj < 4; nj++) {
            int row0 = bM + wm + 16 * mi + rA;
            int col0 = bN + wn + 8 * nj + 2 * t4;
            float bv0 = bias[col0], bv1 = bias[col0 + 1];
            float v00 = (acc[mi][nj][0] + bv0) * scale;
            float v01 = (acc[mi][nj][1] + bv1) * scale;
            float v10 = (acc[mi][nj][2] + bv0) * scale;
            float v11 = (acc[mi][nj][3] + bv1) * scale;
            if (qkv_mode) {
                int b0 = row0 >> 11, t0 = row0 & 2047;
                int h0 = col0 >> 6, d0 = col0 & 63;
                long i00 = ((long)((b0 << 4) + h0) * 2048 + t0) * 64 + d0;
                int rowb = row0 + 8;
                int b1 = rowb >> 11, t1 = rowb & 2047;
                long i10 = ((long)((b1 << 4) + h0) * 2048 + t1) * 64 + d0;
                C[i00]     = v00;
                C[i00 + 1] = v01;
                C[i10]     = v10;
                C[i10 + 1] = v11;
            } else {
                C[(long)row0 * 1024 + col0]       = v00;
                C[(long)row0 * 1024 + col0 + 1]   = v01;
                C[(long)(row0 + 8) * 1024 + col0]     = v10;
                C[(long)(row0 + 8) * 1024 + col0 + 1] = v11;
            }
        }
    }
}

// ------------------------------------------------------------
// Flash attention: per block one (bh, q-tile of 64). 4 warps x 16 q-rows.
// S = Q@K^T (tf32), online softmax, O += P@V. P reuses Ks smem per-warp.
// Output written as [B*T, E] row-major (input to output projection).
// ------------------------------------------------------------
__global__ __launch_bounds__(128) void attn_kernel(
    const float* __restrict__ Q, const float* __restrict__ K,
    const float* __restrict__ V, float* __restrict__ O)
{
    __shared__ float Ks[64][68];   // [key/q-row][d]; reused to stage Q, then P
    __shared__ float Vts[64][69];  // [d][key]

    const int tid  = threadIdx.x;
    const int lane = tid & 31;
    const int warp = tid >> 5;
    const int rA = lane >> 2;
    const int t4 = lane & 3;
    const int bh = blockIdx.y;     // 0..63  (b*16 + h)
    const int qt = blockIdx.x;     // 0..31

    const float* Qb = Q + (long)bh * 2048 * 64;
    const float* Kb = K + (long)bh * 2048 * 64;
    const float* Vb = V + (long)bh * 2048 * 64;

    const int lr = tid >> 4;        // 0..7
    const int lc = (tid & 15) * 4;  // 0..60

    // ---- stage Q tile, pull into A-fragments ----
#pragma unroll
    for (int i = 0; i < 8; i++) {
        int row = lr + 8 * i;
        float4 q4 = *(const float4*)(Qb + (long)(qt * 64 + row) * 64 + lc);
        float4 qc = make_float4(f2tf(q4.x), f2tf(q4.y), f2tf(q4.z), f2tf(q4.w));
        *(float4*)&Ks[row][lc] = qc;
    }
    __syncthreads();
    unsigned qf[8][4];
#pragma unroll
    for (int ks = 0; ks < 8; ks++) {
        int k8 = ks * 8;
        int r0 = warp * 16 + rA;
        qf[ks][0] = fau(Ks[r0][k8 + t4]);
        qf[ks][1] = fau(Ks[r0 + 8][k8 + t4]);
        qf[ks][2] = fau(Ks[r0][k8 + 4 + t4]);
        qf[ks][3] = fau(Ks[r0 + 8][k8 + 4 + t4]);
    }
    __syncthreads();

    float oacc[8][4];
#pragma unroll
    for (int j = 0; j < 8; j++)
#pragma unroll
        for (int e = 0; e < 4; e++) oacc[j][e] = 0.f;
    float mA = -INFINITY, mB = -INFINITY, lAcc = 0.f, lBcc = 0.f;

    for (int kt = 0; kt < 32; kt++) {
        const float* Kt = Kb + (long)kt * 64 * 64;
        const float* Vt = Vb + (long)kt * 64 * 64;
#pragma unroll
        for (int i = 0; i < 8; i++) {
            int row = lr + 8 * i;
            float4 k4 = *(const float4*)(Kt + row * 64 + lc);
            float4 kc = make_float4(f2tf(k4.x), f2tf(k4.y), f2tf(k4.z), f2tf(k4.w));
            *(float4*)&Ks[row][lc] = kc;
            float4 v4 = *(const float4*)(Vt + row * 64 + lc);
            Vts[lc + 0][row] = f2tf(v4.x);
            Vts[lc + 1][row] = f2tf(v4.y);
            Vts[lc + 2][row] = f2tf(v4.z);
            Vts[lc + 3][row] = f2tf(v4.w);
        }
        __syncthreads();

        // ---- S = Q @ K^T ----
        float sacc[8][4];
#pragma unroll
        for (int j = 0; j < 8; j++)
#pragma unroll
            for (int e = 0; e < 4; e++) sacc[j][e] = 0.f;
#pragma unroll
        for (int ks = 0; ks < 8; ks++) {
            int k8 = ks * 8;
#pragma unroll
            for (int nj = 0; nj < 8; nj++) {
                unsigned b0 = fau(Ks[nj * 8 + rA][k8 + t4]);
                unsigned b1 = fau(Ks[nj * 8 + rA][k8 + 4 + t4]);
                mma_tf32(sacc[nj][0], sacc[nj][1], sacc[nj][2], sacc[nj][3],
                         qf[ks][0], qf[ks][1], qf[ks][2], qf[ks][3], b0, b1);
            }
        }
        __syncthreads();   // all warps done reading Ks; about to overwrite with P

        // ---- online softmax ----
        float mxA = -INFINITY, mxB = -INFINITY;
#pragma unroll
        for (int nj = 0; nj < 8; nj++) {
            mxA = fmaxf(mxA, fmaxf(sacc[nj][0], sacc[nj][1]));
            mxB = fmaxf(mxB, fmaxf(sacc[nj][2], sacc[nj][3]));
        }
        mxA = fmaxf(mxA, __shfl_xor_sync(0xffffffffu, mxA, 1));
        mxA = fmaxf(mxA, __shfl_xor_sync(0xffffffffu, mxA, 2));
        mxB = fmaxf(mxB, __shfl_xor_sync(0xffffffffu, mxB, 1));
        mxB = fmaxf(mxB, __shfl_xor_sync(0xffffffffu, mxB, 2));
        float nmA = fmaxf(mA, mxA), nmB = fmaxf(mB, mxB);
        float aA = __expf(mA - nmA), aB = __expf(mB - nmB);
        float sA = 0.f, sB = 0.f;
#pragma unroll
        for (int nj = 0; nj < 8; nj++) {
            sacc[nj][0] = __expf(sacc[nj][0] - nmA); sA += sacc[nj][0];
            sacc[nj][1] = __expf(sacc[nj][1] - nmA); sA += sacc[nj][1];
            sacc[nj][2] = __expf(sacc[nj][2] - nmB); sB += sacc[nj][2];
            sacc[nj][3] = __expf(sacc[nj][3] - nmB); sB += sacc[nj][3];
        }
        sA += __shfl_xor_sync(0xffffffffu, sA, 1);
        sA += __shfl_xor_sync(0xffffffffu, sA, 2);
        sB += __shfl_xor_sync(0xffffffffu, sB, 1);
        sB += __shfl_xor_sync(0xffffffffu, sB, 2);
        lAcc = lAcc * aA + sA;  mA = nmA;
        lBcc = lBcc * aB + sB;  mB = nmB;
#pragma unroll
        for (int nj = 0; nj < 8; nj++) {
            oacc[nj][0] *= aA; oacc[nj][1] *= aA;
            oacc[nj][2] *= aB; oacc[nj][3] *= aB;
        }

        // ---- write P into warp-private rows of Ks ----
        {
            int r0 = warp * 16 + rA;
#pragma unroll
            for (int nj = 0; nj < 8; nj++) {
                int c0 = nj * 8 + 2 * t4;
                Ks[r0][c0]         = f2tf(sacc[nj][0]);
                Ks[r0][c0 + 1]     = f2tf(sacc[nj][1]);
                Ks[r0 + 8][c0]     = f2tf(sacc[nj][2]);
                Ks[r0 + 8][c0 + 1] = f2tf(sacc[nj][3]);
            }
        }
        __syncwarp();

        // ---- O += P @ V ----
#pragma unroll
        for (int ks = 0; ks < 8; ks++) {
            int k8 = ks * 8;
            int r0 = warp * 16 + rA;
            unsigned pf0 = fau(Ks[r0][k8 + t4]);
            unsigned pf1 = fau(Ks[r0 + 8][k8 + t4]);
            unsigned pf2 = fau(Ks[r0][k8 + 4 + t4]);
            unsigned pf3 = fau(Ks[r0 + 8][k8 + 4 + t4]);
#pragma unroll
            for (int nj = 0; nj < 8; nj++) {
                unsigned b0 = fau(Vts[nj * 8 + rA][k8 + t4]);
                unsigned b1 = fau(Vts[nj * 8 + rA][k8 + 4 + t4]);
                mma_tf32(oacc[nj][0], oacc[nj][1], oacc[nj][2], oacc[nj][3],
                         pf0, pf1, pf2, pf3, b0, b1);
            }
        }
        __syncthreads();  // done with Ks/Vts before next tile load
    }

    // ---- epilogue: O[b*2048+t][h*64+d] ----
    const int bidx = bh >> 4, hidx = bh & 15;
    float iA = 1.f / lAcc, iB = 1.f / lBcc;
    int trow = qt * 64 + warp * 16 + rA;
#pragma unroll
    for (int nj = 0; nj < 8; nj++) {
        int d0 = nj * 8 + 2 * t4;
        long baseA = ((long)bidx * 2048 + trow) * 1024 + hidx * 64 + d0;
        long baseB = ((long)bidx * 2048 + trow + 8) * 1024 + hidx * 64 + d0;
        O[baseA]     = oacc[nj][0] * iA;
        O[baseA + 1] = oacc[nj][1] * iA;
        O[baseB]     = oacc[nj][2] * iB;
        O[baseB + 1] = oacc[nj][3] * iB;
    }
}

// ------------------------------------------------------------
extern "C" void kernel_launch(void* const* d_in, const int* in_sizes, int n_in,
                              void* d_out, int out_size) {
    (void)in_sizes; (void)n_in; (void)out_size;
    const float* x  = (const float*)d_in[0];
    const float* Wq = (const float*)d_in[1];
    const float* bq = (const float*)d_in[2];
    const float* Wk = (const float*)d_in[3];
    const float* bk = (const float*)d_in[4];
    const float* Wv = (const float*)d_in[5];
    const float* bv = (const float*)d_in[6];
    const float* Wo = (const float*)d_in[7];
    const float* bo = (const float*)d_in[8];
    float* out = (float*)d_out;

    void *pq, *pk, *pv, *pa;
    cudaGetSymbolAddress(&pq, g_q);
    cudaGetSymbolAddress(&pk, g_k);
    cudaGetSymbolAddress(&pv, g_v);
    cudaGetSymbolAddress(&pa, g_ao);
    float* qb = (float*)pq;
    float* kb = (float*)pk;
    float* vb = (float*)pv;
    float* ab = (float*)pa;

    dim3 gg(8, 64);   // N blocks x M blocks (1024/128, 8192/128)
    gemm_tf32_kernel<<<gg, 256>>>(x, Wq, bq, qb, 0.125f, 1);
    gemm_tf32_kernel<<<gg, 256>>>(x, Wk, bk, kb, 1.0f, 1);
    gemm_tf32_kernel<<<gg, 256>>>(x, Wv, bv, vb, 1.0f, 1);
    attn_kernel<<<dim3(32, 64), 128>>>(qb, kb, vb, ab);
    gemm_tf32_kernel<<<gg, 256>>>(ab, Wo, bo, out, 1.0f, 0);
}

// round 7
// speedup vs baseline: 1.2457x; 1.2457x over previous
#include <cuda_runtime.h>
#include <cstdint>

// ============================================================
// MultiHeadAttention: B=4, T=2048, E=1024, H=16, D=64
// tf32 mma.sync + cp.async double-buffering end-to-end
// ============================================================

#define DINL __device__ __forceinline__

DINL float f2tf(float x) {
    unsigned u;
    asm("cvt.rna.tf32.f32 %0, %1;" : "=r"(u) : "f"(x));
    return __uint_as_float(u);
}
DINL unsigned fau(float x) { return __float_as_uint(x); }
DINL unsigned su32(const void* p) {
    unsigned a;
    asm("{.reg .u64 t; cvta.to.shared.u64 t, %1; cvt.u32.u64 %0, t;}" : "=r"(a) : "l"(p));
    return a;
}
DINL void cp16(unsigned dst, const void* src) {
    asm volatile("cp.async.cg.shared.global [%0], [%1], 16;" :: "r"(dst), "l"(src));
}
DINL void cp_commit() { asm volatile("cp.async.commit_group;" ::: "memory"); }
DINL void cp_wait1()  { asm volatile("cp.async.wait_group 1;" ::: "memory"); }
DINL void cp_wait0()  { asm volatile("cp.async.wait_group 0;" ::: "memory"); }

DINL void mma_tf32(float& c0, float& c1, float& c2, float& c3,
                   unsigned a0, unsigned a1, unsigned a2, unsigned a3,
                   unsigned b0, unsigned b1) {
    asm volatile(
        "mma.sync.aligned.m16n8k8.row.col.f32.tf32.tf32.f32 "
        "{%0,%1,%2,%3}, {%4,%5,%6,%7}, {%8,%9}, {%0,%1,%2,%3};\n"
        : "+f"(c0), "+f"(c1), "+f"(c2), "+f"(c3)
        : "r"(a0), "r"(a1), "r"(a2), "r"(a3), "r"(b0), "r"(b1));
}

// Scratch buffers
__device__ float g_q[8388608];   // Q [B*H, T, D] (tf32, pre-scaled)
__device__ float g_k[8388608];   // K
__device__ float g_v[8388608];   // V
__device__ float g_ao[8388608];  // attention out [B*T, E] (tf32)
__device__ float g_xc[8388608];  // x converted to tf32
__device__ float g_wq[1048576];
__device__ float g_wk[1048576];
__device__ float g_wv[1048576];
__device__ float g_wo[1048576];

// ------------------------------------------------------------
// Elementwise fp32 -> tf32 (RNA) conversion
// ------------------------------------------------------------
__global__ __launch_bounds__(256) void cvt_kernel(
    const float* __restrict__ in, float* __restrict__ out, int n4)
{
    int i = blockIdx.x * 256 + threadIdx.x;
    if (i < n4) {
        float4 v = ((const float4*)in)[i];
        v.x = f2tf(v.x); v.y = f2tf(v.y); v.z = f2tf(v.z); v.w = f2tf(v.w);
        ((float4*)out)[i] = v;
    }
}

// ------------------------------------------------------------
// GEMM: C = (A[M,1024] @ W[1024,1024]^T + bias) * scale
// A, W already tf32. cp.async double-buffered, K-tile 32.
// 256 threads (8 warps 2x4, warp tile 64x32), block tile 128x128.
// qkv_mode=1: out[((b*16+h)*2048+t)*64+d], tf32-rounded output
// qkv_mode=0: row-major fp32 (final output)
// ------------------------------------------------------------
__global__ __launch_bounds__(256, 2) void gemm_tf32_kernel(
    const float* __restrict__ A, const float* __restrict__ W,
    const float* __restrict__ bias, float* __restrict__ C,
    float scale, int qkv_mode)
{
    extern __shared__ float sm[];
    float* As = sm;            // [2][128][36]
    float* Bs = sm + 9216;     // [2][128][36]
    const unsigned as_u = su32(As), bs_u = su32(Bs);

    const int tid  = threadIdx.x;
    const int lane = tid & 31;
    const int warp = tid >> 5;
    const int wm = (warp >> 2) * 64;
    const int wn = (warp & 3) * 32;
    const int bM = blockIdx.y * 128;
    const int bN = blockIdx.x * 128;
    const int rA = lane >> 2;
    const int t4 = lane & 3;

    float acc[4][4][4];
#pragma unroll
    for (int i = 0; i < 4; i++)
#pragma unroll
        for (int j = 0; j < 4; j++)
#pragma unroll
            for (int e = 0; e < 4; e++) acc[i][j][e] = 0.f;

    auto issue = [&](int kt, int buf) {
#pragma unroll
        for (int i = 0; i < 4; i++) {
            int idx = tid + 256 * i;          // 1024 16B-chunks per operand
            int row = idx >> 3;
            int ch  = (idx & 7) * 4;
            cp16(as_u + (unsigned)(buf * 4608 + row * 36 + ch) * 4,
                 A + (long)(bM + row) * 1024 + kt + ch);
            cp16(bs_u + (unsigned)(buf * 4608 + row * 36 + ch) * 4,
                 W + (long)(bN + row) * 1024 + kt + ch);
        }
    };

    issue(0, 0); cp_commit();

    for (int ki = 0; ki < 32; ki++) {
        if (ki < 31) { issue((ki + 1) * 32, (ki + 1) & 1); cp_commit(); cp_wait1(); }
        else cp_wait0();
        __syncthreads();

        const float* Ab = As + (ki & 1) * 4608;
        const float* Bb = Bs + (ki & 1) * 4608;

#pragma unroll
        for (int kk = 0; kk < 32; kk += 8) {
            unsigned af[4][4], bf[4][2];
#pragma unroll
            for (int mi = 0; mi < 4; mi++) {
                int r0 = wm + 16 * mi + rA;
                af[mi][0] = fau(Ab[r0 * 36 + kk + t4]);
                af[mi][1] = fau(Ab[(r0 + 8) * 36 + kk + t4]);
                af[mi][2] = fau(Ab[r0 * 36 + kk + 4 + t4]);
                af[mi][3] = fau(Ab[(r0 + 8) * 36 + kk + 4 + t4]);
            }
#pragma unroll
            for (int nj = 0; nj < 4; nj++) {
                int c0 = wn + 8 * nj + rA;
                bf[nj][0] = fau(Bb[c0 * 36 + kk + t4]);
                bf[nj][1] = fau(Bb[c0 * 36 + kk + 4 + t4]);
            }
#pragma unroll
            for (int mi = 0; mi < 4; mi++)
#pragma unroll
                for (int nj = 0; nj < 4; nj++)
                    mma_tf32(acc[mi][nj][0], acc[mi][nj][1], acc[mi][nj][2], acc[mi][nj][3],
                             af[mi][0], af[mi][1], af[mi][2], af[mi][3],
                             bf[nj][0], bf[nj][1]);
        }
        __syncthreads();
    }

    // epilogue
#pragma unroll
    for (int mi = 0; mi < 4; mi++) {
#pragma unroll
        for (int nj = 0; nj < 4; nj++) {
            int row0 = bM + wm + 16 * mi + rA;
            int col0 = bN + wn + 8 * nj + 2 * t4;
            float bv0 = bias[col0], bv1 = bias[col0 + 1];
            float v00 = (acc[mi][nj][0] + bv0) * scale;
            float v01 = (acc[mi][nj][1] + bv1) * scale;
            float v10 = (acc[mi][nj][2] + bv0) * scale;
            float v11 = (acc[mi][nj][3] + bv1) * scale;
            if (qkv_mode) {
                int b0 = row0 >> 11, t0 = row0 & 2047;
                int h0 = col0 >> 6, d0 = col0 & 63;
                long i00 = ((long)((b0 << 4) + h0) * 2048 + t0) * 64 + d0;
                int rowb = row0 + 8;
                int b1 = rowb >> 11, t1 = rowb & 2047;
                long i10 = ((long)((b1 << 4) + h0) * 2048 + t1) * 64 + d0;
                C[i00]     = f2tf(v00);
                C[i00 + 1] = f2tf(v01);
                C[i10]     = f2tf(v10);
                C[i10 + 1] = f2tf(v11);
            } else {
                C[(long)row0 * 1024 + col0]           = v00;
                C[(long)row0 * 1024 + col0 + 1]       = v01;
                C[(long)(row0 + 8) * 1024 + col0]     = v10;
                C[(long)(row0 + 8) * 1024 + col0 + 1] = v11;
            }
        }
    }
}

// ------------------------------------------------------------
// Flash attention: q-tile 128 (8 warps x m16), k-tile 64.
// K and V stored NATURALLY in smem (no permutation). The S-accumulator
// fragment is rebound directly as the P@V A-fragment (a0=c0,a1=c2,a2=c1,a3=c3),
// which relabels hardware k-slot t4 -> key 2t4 and t4+4 -> key 2t4+1.
// The V (B-operand) reads use the SAME relabeling: b0 = row 2t4, b1 = row 2t4+1.
// P never leaves registers. K/V double-buffered via cp.async, both ld=68
// (conflict-free for both the K d-major reads and the strided V reads).
// ------------------------------------------------------------
__global__ __launch_bounds__(256, 2) void attn_kernel(
    const float* __restrict__ Q, const float* __restrict__ K,
    const float* __restrict__ V, float* __restrict__ O)
{
    extern __shared__ float sm[];
    float* Ks = sm;            // [2][64][68]; also Q staging as [128][68]
    float* Vs = sm + 8704;     // [2][64][68], natural [key][d]
    const unsigned ks_u = su32(Ks), vs_u = su32(Vs);

    const int tid  = threadIdx.x;
    const int lane = tid & 31;
    const int warp = tid >> 5;          // 0..7
    const int rA = lane >> 2;
    const int t4 = lane & 3;
    const int bh = blockIdx.y;          // b*16+h
    const int qt = blockIdx.x;          // 0..15

    const float* Qb = Q + (long)bh * 131072;
    const float* Kb = K + (long)bh * 131072;
    const float* Vb = V + (long)bh * 131072;

    // ---- stage Q tile (128x64, already tf32) and pull A-fragments ----
#pragma unroll
    for (int i = 0; i < 8; i++) {
        int idx = tid + 256 * i;        // 2048 chunks
        int row = idx >> 4;
        int ch  = (idx & 15) * 4;
        float4 v = *(const float4*)(Qb + (long)(qt * 128 + row) * 64 + ch);
        *(float4*)(Ks + row * 68 + ch) = v;
    }
    __syncthreads();
    unsigned qf[8][4];
    const int r0 = warp * 16 + rA;
#pragma unroll
    for (int ks = 0; ks < 8; ks++) {
        int k8 = ks * 8;
        qf[ks][0] = fau(Ks[r0 * 68 + k8 + t4]);
        qf[ks][1] = fau(Ks[(r0 + 8) * 68 + k8 + t4]);
        qf[ks][2] = fau(Ks[r0 * 68 + k8 + 4 + t4]);
        qf[ks][3] = fau(Ks[(r0 + 8) * 68 + k8 + 4 + t4]);
    }
    __syncthreads();

    float oacc[8][4];
#pragma unroll
    for (int j = 0; j < 8; j++)
#pragma unroll
        for (int e = 0; e < 4; e++) oacc[j][e] = 0.f;
    float mA = -INFINITY, mB = -INFINITY, lA = 0.f, lB = 0.f;

    auto issueKV = [&](int kt, int buf) {
        const float* Kt = Kb + (long)kt * 4096;
        const float* Vt = Vb + (long)kt * 4096;
#pragma unroll
        for (int i = 0; i < 4; i++) {
            int idx = tid + 256 * i;    // 1024 chunks per operand
            int row = idx >> 4;
            int ch  = (idx & 15) * 4;
            cp16(ks_u + (unsigned)(buf * 4352 + row * 68 + ch) * 4, Kt + row * 64 + ch);
            cp16(vs_u + (unsigned)(buf * 4352 + row * 68 + ch) * 4, Vt + row * 64 + ch);
        }
    };

    issueKV(0, 0); cp_commit();

    for (int kt = 0; kt < 32; kt++) {
        if (kt < 31) { issueKV(kt + 1, (kt + 1) & 1); cp_commit(); cp_wait1(); }
        else cp_wait0();
        __syncthreads();

        const float* Kc = Ks + (kt & 1) * 4352;
        const float* Vc = Vs + (kt & 1) * 4352;

        // ---- S = Q @ K^T ----
        float sacc[8][4];
#pragma unroll
        for (int j = 0; j < 8; j++)
#pragma unroll
            for (int e = 0; e < 4; e++) sacc[j][e] = 0.f;
#pragma unroll
        for (int ks = 0; ks < 8; ks++) {
            int k8 = ks * 8;
#pragma unroll
            for (int nj = 0; nj < 8; nj++) {
                unsigned b0 = fau(Kc[(nj * 8 + rA) * 68 + k8 + t4]);
                unsigned b1 = fau(Kc[(nj * 8 + rA) * 68 + k8 + 4 + t4]);
                mma_tf32(sacc[nj][0], sacc[nj][1], sacc[nj][2], sacc[nj][3],
                         qf[ks][0], qf[ks][1], qf[ks][2], qf[ks][3], b0, b1);
            }
        }

        // ---- online softmax ----
        float mxA = -INFINITY, mxB = -INFINITY;
#pragma unroll
        for (int nj = 0; nj < 8; nj++) {
            mxA = fmaxf(mxA, fmaxf(sacc[nj][0], sacc[nj][1]));
            mxB = fmaxf(mxB, fmaxf(sacc[nj][2], sacc[nj][3]));
        }
        mxA = fmaxf(mxA, __shfl_xor_sync(0xffffffffu, mxA, 1));
        mxA = fmaxf(mxA, __shfl_xor_sync(0xffffffffu, mxA, 2));
        mxB = fmaxf(mxB, __shfl_xor_sync(0xffffffffu, mxB, 1));
        mxB = fmaxf(mxB, __shfl_xor_sync(0xffffffffu, mxB, 2));
        float nmA = fmaxf(mA, mxA), nmB = fmaxf(mB, mxB);
        float aAf = __expf(mA - nmA), aBf = __expf(mB - nmB);
        float sA = 0.f, sB = 0.f;
#pragma unroll
        for (int nj = 0; nj < 8; nj++) {
            sacc[nj][0] = __expf(sacc[nj][0] - nmA); sA += sacc[nj][0];
            sacc[nj][1] = __expf(sacc[nj][1] - nmA); sA += sacc[nj][1];
            sacc[nj][2] = __expf(sacc[nj][2] - nmB); sB += sacc[nj][2];
            sacc[nj][3] = __expf(sacc[nj][3] - nmB); sB += sacc[nj][3];
        }
        sA += __shfl_xor_sync(0xffffffffu, sA, 1);
        sA += __shfl_xor_sync(0xffffffffu, sA, 2);
        sB += __shfl_xor_sync(0xffffffffu, sB, 1);
        sB += __shfl_xor_sync(0xffffffffu, sB, 2);
        lA = lA * aAf + sA;  mA = nmA;
        lB = lB * aBf + sB;  mB = nmB;
#pragma unroll
        for (int nj = 0; nj < 8; nj++) {
            oacc[nj][0] *= aAf; oacc[nj][1] *= aAf;
            oacc[nj][2] *= aBf; oacc[nj][3] *= aBf;
        }

        // ---- O += P @ V ----
        // A rebind: hardware k-slot t4 carries key k8+2t4 (a0=c0, a1=c2),
        //           slot t4+4 carries key k8+2t4+1 (a2=c1, a3=c3).
        // B reads the matching V rows: b0 = V[k8+2t4], b1 = V[k8+2t4+1].
#pragma unroll
        for (int ks = 0; ks < 8; ks++) {
            int k8 = ks * 8;
            unsigned a0 = fau(f2tf(sacc[ks][0]));
            unsigned a1 = fau(f2tf(sacc[ks][2]));
            unsigned a2 = fau(f2tf(sacc[ks][1]));
            unsigned a3 = fau(f2tf(sacc[ks][3]));
#pragma unroll
            for (int nj = 0; nj < 8; nj++) {
                unsigned b0 = fau(Vc[(k8 + 2 * t4) * 68 + nj * 8 + rA]);
                unsigned b1 = fau(Vc[(k8 + 2 * t4 + 1) * 68 + nj * 8 + rA]);
                mma_tf32(oacc[nj][0], oacc[nj][1], oacc[nj][2], oacc[nj][3],
                         a0, a1, a2, a3, b0, b1);
            }
        }
        __syncthreads();
    }

    // ---- epilogue: O[b*2048+t][h*64+d], tf32-rounded for final GEMM ----
    const int bidx = bh >> 4, hidx = bh & 15;
    float iA = 1.f / lA, iB = 1.f / lB;
    int trow = qt * 128 + warp * 16 + rA;
#pragma unroll
    for (int nj = 0; nj < 8; nj++) {
        int d0 = nj * 8 + 2 * t4;
        long baseA = ((long)bidx * 2048 + trow) * 1024 + hidx * 64 + d0;
        long baseB = baseA + 8 * 1024;
        float2 vA = make_float2(f2tf(oacc[nj][0] * iA), f2tf(oacc[nj][1] * iA));
        float2 vB = make_float2(f2tf(oacc[nj][2] * iB), f2tf(oacc[nj][3] * iB));
        *(float2*)(O + baseA) = vA;
        *(float2*)(O + baseB) = vB;
    }
}

// ------------------------------------------------------------
extern "C" void kernel_launch(void* const* d_in, const int* in_sizes, int n_in,
                              void* d_out, int out_size) {
    (void)in_sizes; (void)n_in; (void)out_size;
    const float* x  = (const float*)d_in[0];
    const float* Wq = (const float*)d_in[1];
    const float* bq = (const float*)d_in[2];
    const float* Wk = (const float*)d_in[3];
    const float* bk = (const float*)d_in[4];
    const float* Wv = (const float*)d_in[5];
    const float* bv = (const float*)d_in[6];
    const float* Wo = (const float*)d_in[7];
    const float* bo = (const float*)d_in[8];
    float* out = (float*)d_out;

    void *pq, *pk, *pv, *pa, *pxc, *pwq, *pwk, *pwv, *pwo;
    cudaGetSymbolAddress(&pq,  g_q);
    cudaGetSymbolAddress(&pk,  g_k);
    cudaGetSymbolAddress(&pv,  g_v);
    cudaGetSymbolAddress(&pa,  g_ao);
    cudaGetSymbolAddress(&pxc, g_xc);
    cudaGetSymbolAddress(&pwq, g_wq);
    cudaGetSymbolAddress(&pwk, g_wk);
    cudaGetSymbolAddress(&pwv, g_wv);
    cudaGetSymbolAddress(&pwo, g_wo);
    float* qb  = (float*)pq;
    float* kb  = (float*)pk;
    float* vb  = (float*)pv;
    float* ab  = (float*)pa;
    float* xc  = (float*)pxc;
    float* wqc = (float*)pwq;
    float* wkc = (float*)pwk;
    float* wvc = (float*)pwv;
    float* woc = (float*)pwo;

    cudaFuncSetAttribute(gemm_tf32_kernel,
                         cudaFuncAttributeMaxDynamicSharedMemorySize, 73728);
    cudaFuncSetAttribute(attn_kernel,
                         cudaFuncAttributeMaxDynamicSharedMemorySize, 69632);

    // pre-convert inputs to tf32 (RNA)
    cvt_kernel<<<8192, 256>>>(x,  xc,  2097152);
    cvt_kernel<<<1024, 256>>>(Wq, wqc, 262144);
    cvt_kernel<<<1024, 256>>>(Wk, wkc, 262144);
    cvt_kernel<<<1024, 256>>>(Wv, wvc, 262144);
    cvt_kernel<<<1024, 256>>>(Wo, woc, 262144);

    dim3 gg(8, 64);   // N x M blocks
    gemm_tf32_kernel<<<gg, 256, 73728>>>(xc, wqc, bq, qb, 0.125f, 1);
    gemm_tf32_kernel<<<gg, 256, 73728>>>(xc, wkc, bk, kb, 1.0f, 1);
    gemm_tf32_kernel<<<gg, 256, 73728>>>(xc, wvc, bv, vb, 1.0f, 1);
    attn_kernel<<<dim3(16, 64), 256, 69632>>>(qb, kb, vb, ab);
    gemm_tf32_kernel<<<gg, 256, 73728>>>(ab, woc, bo, out, 1.0f, 0);
}

// round 8
// speedup vs baseline: 1.3742x; 1.1032x over previous
#include <cuda_runtime.h>
#include <cstdint>

// ============================================================
// MultiHeadAttention: B=4, T=2048, E=1024, H=16, D=64
// tf32 mma.sync + cp.async; fused QKV GEMM; 2 m-subtiles/warp attn
// ============================================================

#define DINL __device__ __forceinline__

DINL float f2tf(float x) {
    unsigned u;
    asm("cvt.rna.tf32.f32 %0, %1;" : "=r"(u) : "f"(x));
    return __uint_as_float(u);
}
DINL unsigned fau(float x) { return __float_as_uint(x); }
DINL unsigned su32(const void* p) {
    unsigned a;
    asm("{.reg .u64 t; cvta.to.shared.u64 t, %1; cvt.u32.u64 %0, t;}" : "=r"(a) : "l"(p));
    return a;
}
DINL void cp16(unsigned dst, const void* src) {
    asm volatile("cp.async.cg.shared.global [%0], [%1], 16;" :: "r"(dst), "l"(src));
}
DINL void cp_commit() { asm volatile("cp.async.commit_group;" ::: "memory"); }
DINL void cp_wait0()  { asm volatile("cp.async.wait_group 0;" ::: "memory"); }

DINL void mma_tf32(float& c0, float& c1, float& c2, float& c3,
                   unsigned a0, unsigned a1, unsigned a2, unsigned a3,
                   unsigned b0, unsigned b1) {
    asm volatile(
        "mma.sync.aligned.m16n8k8.row.col.f32.tf32.tf32.f32 "
        "{%0,%1,%2,%3}, {%4,%5,%6,%7}, {%8,%9}, {%0,%1,%2,%3};\n"
        : "+f"(c0), "+f"(c1), "+f"(c2), "+f"(c3)
        : "r"(a0), "r"(a1), "r"(a2), "r"(a3), "r"(b0), "r"(b1));
}

// Scratch buffers
__device__ float g_q[8388608];    // Q [B*H, T, D] (tf32, pre-scaled)
__device__ float g_k[8388608];    // K
__device__ float g_v[8388608];    // V
__device__ float g_ao[8388608];   // attention out [B*T, E] (tf32)
__device__ float g_xc[8388608];   // x converted to tf32
__device__ float g_wqkv[3145728]; // Wq|Wk|Wv concatenated, tf32
__device__ float g_wo[1048576];   // Wo tf32

// ------------------------------------------------------------
// fp32 -> tf32 converts
// ------------------------------------------------------------
__global__ __launch_bounds__(256) void cvt_x_kernel(
    const float* __restrict__ in, float* __restrict__ out)
{
    int i = blockIdx.x * 256 + threadIdx.x;
    float4 v = ((const float4*)in)[i];
    v.x = f2tf(v.x); v.y = f2tf(v.y); v.z = f2tf(v.z); v.w = f2tf(v.w);
    ((float4*)out)[i] = v;
}

// grid.y: 0..2 -> wqkv slab y, 3 -> wo
__global__ __launch_bounds__(256) void cvt_w_kernel(
    const float* __restrict__ wq, const float* __restrict__ wk,
    const float* __restrict__ wv, const float* __restrict__ wo,
    float* __restrict__ dqkv, float* __restrict__ dwo)
{
    int y = blockIdx.y;
    const float* src = (y == 0) ? wq : (y == 1) ? wk : (y == 2) ? wv : wo;
    float* dst = (y < 3) ? (dqkv + (long)y * 1048576) : dwo;
    int i = blockIdx.x * 256 + threadIdx.x;   // 262144 float4 per matrix
    float4 v = ((const float4*)src)[i];
    v.x = f2tf(v.x); v.y = f2tf(v.y); v.z = f2tf(v.z); v.w = f2tf(v.w);
    ((float4*)dst)[i] = v;
}

// ------------------------------------------------------------
// Fused QKV GEMM: C_p = (x @ W_p^T + b_p) * scale_p, p selected by bN>>10.
// N range 3072 (Wqkv concatenated). Output scattered to [B*H, T, D], tf32.
// 256 threads, block tile 128x128, K-tile 32, cp.async double-buffered.
// ------------------------------------------------------------
__global__ __launch_bounds__(256, 2) void gemm_qkv_kernel(
    const float* __restrict__ A, const float* __restrict__ W,
    const float* __restrict__ bq, const float* __restrict__ bk,
    const float* __restrict__ bv,
    float* __restrict__ Cq, float* __restrict__ Ck, float* __restrict__ Cv)
{
    extern __shared__ float sm[];
    float* As = sm;            // [2][128][36]
    float* Bs = sm + 9216;
    const unsigned as_u = su32(As), bs_u = su32(Bs);

    const int tid  = threadIdx.x;
    const int lane = tid & 31;
    const int warp = tid >> 5;
    const int wm = (warp >> 2) * 64;
    const int wn = (warp & 3) * 32;
    const int bM = blockIdx.y * 128;
    const int bN = blockIdx.x * 128;
    const int p  = bN >> 10;                     // 0=Q,1=K,2=V
    const float scale = (p == 0) ? 0.125f : 1.0f;
    const float* bias = (p == 0) ? bq : (p == 1) ? bk : bv;
    float* C = (p == 0) ? Cq : (p == 1) ? Ck : Cv;
    const int rA = lane >> 2;
    const int t4 = lane & 3;

    float acc[4][4][4];
#pragma unroll
    for (int i = 0; i < 4; i++)
#pragma unroll
        for (int j = 0; j < 4; j++)
#pragma unroll
            for (int e = 0; e < 4; e++) acc[i][j][e] = 0.f;

    auto issue = [&](int kt, int buf) {
#pragma unroll
        for (int i = 0; i < 4; i++) {
            int idx = tid + 256 * i;
            int row = idx >> 3;
            int ch  = (idx & 7) * 4;
            cp16(as_u + (unsigned)(buf * 4608 + row * 36 + ch) * 4,
                 A + (long)(bM + row) * 1024 + kt + ch);
            cp16(bs_u + (unsigned)(buf * 4608 + row * 36 + ch) * 4,
                 W + (long)(bN + row) * 1024 + kt + ch);
        }
    };

    issue(0, 0); cp_commit();

    for (int ki = 0; ki < 32; ki++) {
        cp_wait0();
        __syncthreads();
        if (ki < 31) { issue((ki + 1) * 32, (ki + 1) & 1); cp_commit(); }

        const float* Ab = As + (ki & 1) * 4608;
        const float* Bb = Bs + (ki & 1) * 4608;

#pragma unroll
        for (int kk = 0; kk < 32; kk += 8) {
            unsigned af[4][4], bf[4][2];
#pragma unroll
            for (int mi = 0; mi < 4; mi++) {
                int r0 = wm + 16 * mi + rA;
                af[mi][0] = fau(Ab[r0 * 36 + kk + t4]);
                af[mi][1] = fau(Ab[(r0 + 8) * 36 + kk + t4]);
                af[mi][2] = fau(Ab[r0 * 36 + kk + 4 + t4]);
                af[mi][3] = fau(Ab[(r0 + 8) * 36 + kk + 4 + t4]);
            }
#pragma unroll
            for (int nj = 0; nj < 4; nj++) {
                int c0 = wn + 8 * nj + rA;
                bf[nj][0] = fau(Bb[c0 * 36 + kk + t4]);
                bf[nj][1] = fau(Bb[c0 * 36 + kk + 4 + t4]);
            }
#pragma unroll
            for (int mi = 0; mi < 4; mi++)
#pragma unroll
                for (int nj = 0; nj < 4; nj++)
                    mma_tf32(acc[mi][nj][0], acc[mi][nj][1], acc[mi][nj][2], acc[mi][nj][3],
                             af[mi][0], af[mi][1], af[mi][2], af[mi][3],
                             bf[nj][0], bf[nj][1]);
        }
    }

#pragma unroll
    for (int mi = 0; mi < 4; mi++) {
#pragma unroll
        for (int nj = 0; nj < 4; nj++) {
            int row0 = bM + wm + 16 * mi + rA;
            int coln = bN + wn + 8 * nj + 2 * t4;   // 0..3071
            int c    = coln & 1023;
            float bv0 = bias[c], bv1 = bias[c + 1];
            float v00 = (acc[mi][nj][0] + bv0) * scale;
            float v01 = (acc[mi][nj][1] + bv1) * scale;
            float v10 = (acc[mi][nj][2] + bv0) * scale;
            float v11 = (acc[mi][nj][3] + bv1) * scale;
            int h0 = c >> 6, d0 = c & 63;
            int b0 = row0 >> 11, t0 = row0 & 2047;
            long i00 = ((long)((b0 << 4) + h0) * 2048 + t0) * 64 + d0;
            int rowb = row0 + 8;
            int b1 = rowb >> 11, t1 = rowb & 2047;
            long i10 = ((long)((b1 << 4) + h0) * 2048 + t1) * 64 + d0;
            C[i00]     = f2tf(v00);
            C[i00 + 1] = f2tf(v01);
            C[i10]     = f2tf(v10);
            C[i10 + 1] = f2tf(v11);
        }
    }
}

// ------------------------------------------------------------
// Output projection GEMM: out = A @ Wo^T + bo, row-major fp32.
// ------------------------------------------------------------
__global__ __launch_bounds__(256, 2) void gemm_o_kernel(
    const float* __restrict__ A, const float* __restrict__ W,
    const float* __restrict__ bias, float* __restrict__ C)
{
    extern __shared__ float sm[];
    float* As = sm;
    float* Bs = sm + 9216;
    const unsigned as_u = su32(As), bs_u = su32(Bs);

    const int tid  = threadIdx.x;
    const int lane = tid & 31;
    const int warp = tid >> 5;
    const int wm = (warp >> 2) * 64;
    const int wn = (warp & 3) * 32;
    const int bM = blockIdx.y * 128;
    const int bN = blockIdx.x * 128;
    const int rA = lane >> 2;
    const int t4 = lane & 3;

    float acc[4][4][4];
#pragma unroll
    for (int i = 0; i < 4; i++)
#pragma unroll
        for (int j = 0; j < 4; j++)
#pragma unroll
            for (int e = 0; e < 4; e++) acc[i][j][e] = 0.f;

    auto issue = [&](int kt, int buf) {
#pragma unroll
        for (int i = 0; i < 4; i++) {
            int idx = tid + 256 * i;
            int row = idx >> 3;
            int ch  = (idx & 7) * 4;
            cp16(as_u + (unsigned)(buf * 4608 + row * 36 + ch) * 4,
                 A + (long)(bM + row) * 1024 + kt + ch);
            cp16(bs_u + (unsigned)(buf * 4608 + row * 36 + ch) * 4,
                 W + (long)(bN + row) * 1024 + kt + ch);
        }
    };

    issue(0, 0); cp_commit();

    for (int ki = 0; ki < 32; ki++) {
        cp_wait0();
        __syncthreads();
        if (ki < 31) { issue((ki + 1) * 32, (ki + 1) & 1); cp_commit(); }

        const float* Ab = As + (ki & 1) * 4608;
        const float* Bb = Bs + (ki & 1) * 4608;

#pragma unroll
        for (int kk = 0; kk < 32; kk += 8) {
            unsigned af[4][4], bf[4][2];
#pragma unroll
            for (int mi = 0; mi < 4; mi++) {
                int r0 = wm + 16 * mi + rA;
                af[mi][0] = fau(Ab[r0 * 36 + kk + t4]);
                af[mi][1] = fau(Ab[(r0 + 8) * 36 + kk + t4]);
                af[mi][2] = fau(Ab[r0 * 36 + kk + 4 + t4]);
                af[mi][3] = fau(Ab[(r0 + 8) * 36 + kk + 4 + t4]);
            }
#pragma unroll
            for (int nj = 0; nj < 4; nj++) {
                int c0 = wn + 8 * nj + rA;
                bf[nj][0] = fau(Bb[c0 * 36 + kk + t4]);
                bf[nj][1] = fau(Bb[c0 * 36 + kk + 4 + t4]);
            }
#pragma unroll
            for (int mi = 0; mi < 4; mi++)
#pragma unroll
                for (int nj = 0; nj < 4; nj++)
                    mma_tf32(acc[mi][nj][0], acc[mi][nj][1], acc[mi][nj][2], acc[mi][nj][3],
                             af[mi][0], af[mi][1], af[mi][2], af[mi][3],
                             bf[nj][0], bf[nj][1]);
        }
    }

#pragma unroll
    for (int mi = 0; mi < 4; mi++) {
#pragma unroll
        for (int nj = 0; nj < 4; nj++) {
            int row0 = bM + wm + 16 * mi + rA;
            int col0 = bN + wn + 8 * nj + 2 * t4;
            float bv0 = bias[col0], bv1 = bias[col0 + 1];
            C[(long)row0 * 1024 + col0]           = acc[mi][nj][0] + bv0;
            C[(long)row0 * 1024 + col0 + 1]       = acc[mi][nj][1] + bv1;
            C[(long)(row0 + 8) * 1024 + col0]     = acc[mi][nj][2] + bv0;
            C[(long)(row0 + 8) * 1024 + col0 + 1] = acc[mi][nj][3] + bv1;
        }
    }
}

// ------------------------------------------------------------
// Flash attention: q-tile 128, 4 warps, 32 q-rows per warp (2 x m16
// subtiles) so each K/V B-fragment load feeds 2 MMAs -> LDS traffic
// halved vs 8-warp/16-row layout. k-tile 64, cp.async double-buffered.
// S accumulator rebound as the P@V A-fragment: hw k-slot t4 -> key
// k8+2t4 (a0=c0,a1=c2), slot t4+4 -> key k8+2t4+1 (a2=c1,a3=c3);
// V (B-operand) reads the matching rows: b0=V[k8+2t4], b1=V[k8+2t4+1].
// ------------------------------------------------------------
__global__ __launch_bounds__(128, 2) void attn_kernel(
    const float* __restrict__ Q, const float* __restrict__ K,
    const float* __restrict__ V, float* __restrict__ O)
{
    extern __shared__ float sm[];
    float* Ks = sm;            // [2][64][68]; also Q staging as [128][68]
    float* Vs = sm + 8704;     // [2][64][68], natural [key][d]
    const unsigned ks_u = su32(Ks), vs_u = su32(Vs);

    const int tid  = threadIdx.x;
    const int lane = tid & 31;
    const int warp = tid >> 5;          // 0..3
    const int rA = lane >> 2;
    const int t4 = lane & 3;
    const int bh = blockIdx.y;          // b*16+h
    const int qt = blockIdx.x;          // 0..15

    const float* Qb = Q + (long)bh * 131072;
    const float* Kb = K + (long)bh * 131072;
    const float* Vb = V + (long)bh * 131072;

    // ---- stage Q tile (128x64, tf32) ----
#pragma unroll
    for (int i = 0; i < 16; i++) {
        int idx = tid + 128 * i;        // 2048 chunks
        int row = idx >> 4;
        int ch  = (idx & 15) * 4;
        float4 v = *(const float4*)(Qb + (long)(qt * 128 + row) * 64 + ch);
        *(float4*)(Ks + row * 68 + ch) = v;
    }
    __syncthreads();

    // A-fragments for 2 m-subtiles (rows warp*32 + {0..15} and +16)
    unsigned qf[2][8][4];
    const int r0 = warp * 32 + rA;
#pragma unroll
    for (int s = 0; s < 2; s++) {
        int rs = r0 + 16 * s;
#pragma unroll
        for (int ks = 0; ks < 8; ks++) {
            int k8 = ks * 8;
            qf[s][ks][0] = fau(Ks[rs * 68 + k8 + t4]);
            qf[s][ks][1] = fau(Ks[(rs + 8) * 68 + k8 + t4]);
            qf[s][ks][2] = fau(Ks[rs * 68 + k8 + 4 + t4]);
            qf[s][ks][3] = fau(Ks[(rs + 8) * 68 + k8 + 4 + t4]);
        }
    }
    __syncthreads();

    float oacc[2][8][4];
#pragma unroll
    for (int s = 0; s < 2; s++)
#pragma unroll
        for (int j = 0; j < 8; j++)
#pragma unroll
            for (int e = 0; e < 4; e++) oacc[s][j][e] = 0.f;
    float mA[2] = {-INFINITY, -INFINITY}, mB[2] = {-INFINITY, -INFINITY};
    float lA[2] = {0.f, 0.f}, lB[2] = {0.f, 0.f};

    auto issueKV = [&](int kt, int buf) {
        const float* Kt = Kb + (long)kt * 4096;
        const float* Vt = Vb + (long)kt * 4096;
#pragma unroll
        for (int i = 0; i < 8; i++) {
            int idx = tid + 128 * i;    // 1024 chunks per operand
            int row = idx >> 4;
            int ch  = (idx & 15) * 4;
            cp16(ks_u + (unsigned)(buf * 4352 + row * 68 + ch) * 4, Kt + row * 64 + ch);
            cp16(vs_u + (unsigned)(buf * 4352 + row * 68 + ch) * 4, Vt + row * 64 + ch);
        }
    };

    issueKV(0, 0); cp_commit();

    for (int kt = 0; kt < 32; kt++) {
        cp_wait0();
        __syncthreads();
        if (kt < 31) { issueKV(kt + 1, (kt + 1) & 1); cp_commit(); }

        const float* Kc = Ks + (kt & 1) * 4352;
        const float* Vc = Vs + (kt & 1) * 4352;

        // ---- S = Q @ K^T (both subtiles share each B-fragment) ----
        float sacc[2][8][4];
#pragma unroll
        for (int s = 0; s < 2; s++)
#pragma unroll
            for (int j = 0; j < 8; j++)
#pragma unroll
                for (int e = 0; e < 4; e++) sacc[s][j][e] = 0.f;
#pragma unroll
        for (int ks = 0; ks < 8; ks++) {
            int k8 = ks * 8;
#pragma unroll
            for (int nj = 0; nj < 8; nj++) {
                unsigned b0 = fau(Kc[(nj * 8 + rA) * 68 + k8 + t4]);
                unsigned b1 = fau(Kc[(nj * 8 + rA) * 68 + k8 + 4 + t4]);
                mma_tf32(sacc[0][nj][0], sacc[0][nj][1], sacc[0][nj][2], sacc[0][nj][3],
                         qf[0][ks][0], qf[0][ks][1], qf[0][ks][2], qf[0][ks][3], b0, b1);
                mma_tf32(sacc[1][nj][0], sacc[1][nj][1], sacc[1][nj][2], sacc[1][nj][3],
                         qf[1][ks][0], qf[1][ks][1], qf[1][ks][2], qf[1][ks][3], b0, b1);
            }
        }

        // ---- online softmax per subtile ----
#pragma unroll
        for (int s = 0; s < 2; s++) {
            float mxA = -INFINITY, mxB = -INFINITY;
#pragma unroll
            for (int nj = 0; nj < 8; nj++) {
                mxA = fmaxf(mxA, fmaxf(sacc[s][nj][0], sacc[s][nj][1]));
                mxB = fmaxf(mxB, fmaxf(sacc[s][nj][2], sacc[s][nj][3]));
            }
            mxA = fmaxf(mxA, __shfl_xor_sync(0xffffffffu, mxA, 1));
            mxA = fmaxf(mxA, __shfl_xor_sync(0xffffffffu, mxA, 2));
            mxB = fmaxf(mxB, __shfl_xor_sync(0xffffffffu, mxB, 1));
            mxB = fmaxf(mxB, __shfl_xor_sync(0xffffffffu, mxB, 2));
            float nmA = fmaxf(mA[s], mxA), nmB = fmaxf(mB[s], mxB);
            float aAf = __expf(mA[s] - nmA), aBf = __expf(mB[s] - nmB);
            float sA = 0.f, sB = 0.f;
#pragma unroll
            for (int nj = 0; nj < 8; nj++) {
                sacc[s][nj][0] = __expf(sacc[s][nj][0] - nmA); sA += sacc[s][nj][0];
                sacc[s][nj][1] = __expf(sacc[s][nj][1] - nmA); sA += sacc[s][nj][1];
                sacc[s][nj][2] = __expf(sacc[s][nj][2] - nmB); sB += sacc[s][nj][2];
                sacc[s][nj][3] = __expf(sacc[s][nj][3] - nmB); sB += sacc[s][nj][3];
            }
            sA += __shfl_xor_sync(0xffffffffu, sA, 1);
            sA += __shfl_xor_sync(0xffffffffu, sA, 2);
            sB += __shfl_xor_sync(0xffffffffu, sB, 1);
            sB += __shfl_xor_sync(0xffffffffu, sB, 2);
            lA[s] = lA[s] * aAf + sA;  mA[s] = nmA;
            lB[s] = lB[s] * aBf + sB;  mB[s] = nmB;
#pragma unroll
            for (int nj = 0; nj < 8; nj++) {
                oacc[s][nj][0] *= aAf; oacc[s][nj][1] *= aAf;
                oacc[s][nj][2] *= aBf; oacc[s][nj][3] *= aBf;
            }
        }

        // ---- O += P @ V (both subtiles share each V B-fragment) ----
#pragma unroll
        for (int ks = 0; ks < 8; ks++) {
            int k8 = ks * 8;
            unsigned a00 = fau(f2tf(sacc[0][ks][0]));
            unsigned a01 = fau(f2tf(sacc[0][ks][2]));
            unsigned a02 = fau(f2tf(sacc[0][ks][1]));
            unsigned a03 = fau(f2tf(sacc[0][ks][3]));
            unsigned a10 = fau(f2tf(sacc[1][ks][0]));
            unsigned a11 = fau(f2tf(sacc[1][ks][2]));
            unsigned a12 = fau(f2tf(sacc[1][ks][1]));
            unsigned a13 = fau(f2tf(sacc[1][ks][3]));
#pragma unroll
            for (int nj = 0; nj < 8; nj++) {
                unsigned b0 = fau(Vc[(k8 + 2 * t4) * 68 + nj * 8 + rA]);
                unsigned b1 = fau(Vc[(k8 + 2 * t4 + 1) * 68 + nj * 8 + rA]);
                mma_tf32(oacc[0][nj][0], oacc[0][nj][1], oacc[0][nj][2], oacc[0][nj][3],
                         a00, a01, a02, a03, b0, b1);
                mma_tf32(oacc[1][nj][0], oacc[1][nj][1], oacc[1][nj][2], oacc[1][nj][3],
                         a10, a11, a12, a13, b0, b1);
            }
        }
        __syncthreads();
    }

    // ---- epilogue: O[b*2048+t][h*64+d], tf32-rounded for final GEMM ----
    const int bidx = bh >> 4, hidx = bh & 15;
#pragma unroll
    for (int s = 0; s < 2; s++) {
        float iA = 1.f / lA[s], iB = 1.f / lB[s];
        int trow = qt * 128 + warp * 32 + 16 * s + rA;
#pragma unroll
        for (int nj = 0; nj < 8; nj++) {
            int d0 = nj * 8 + 2 * t4;
            long baseA = ((long)bidx * 2048 + trow) * 1024 + hidx * 64 + d0;
            long baseB = baseA + 8 * 1024;
            float2 vA = make_float2(f2tf(oacc[s][nj][0] * iA), f2tf(oacc[s][nj][1] * iA));
            float2 vB = make_float2(f2tf(oacc[s][nj][2] * iB), f2tf(oacc[s][nj][3] * iB));
            *(float2*)(O + baseA) = vA;
            *(float2*)(O + baseB) = vB;
        }
    }
}

// ------------------------------------------------------------
extern "C" void kernel_launch(void* const* d_in, const int* in_sizes, int n_in,
                              void* d_out, int out_size) {
    (void)in_sizes; (void)n_in; (void)out_size;
    const float* x  = (const float*)d_in[0];
    const float* Wq = (const float*)d_in[1];
    const float* bq = (const float*)d_in[2];
    const float* Wk = (const float*)d_in[3];
    const float* bk = (const float*)d_in[4];
    const float* Wv = (const float*)d_in[5];
    const float* bv = (const float*)d_in[6];
    const float* Wo = (const float*)d_in[7];
    const float* bo = (const float*)d_in[8];
    float* out = (float*)d_out;

    void *pq, *pk, *pv, *pa, *pxc, *pwqkv, *pwo;
    cudaGetSymbolAddress(&pq,    g_q);
    cudaGetSymbolAddress(&pk,    g_k);
    cudaGetSymbolAddress(&pv,    g_v);
    cudaGetSymbolAddress(&pa,    g_ao);
    cudaGetSymbolAddress(&pxc,   g_xc);
    cudaGetSymbolAddress(&pwqkv, g_wqkv);
    cudaGetSymbolAddress(&pwo,   g_wo);
    float* qb   = (float*)pq;
    float* kb   = (float*)pk;
    float* vb   = (float*)pv;
    float* ab   = (float*)pa;
    float* xc   = (float*)pxc;
    float* wqkv = (float*)pwqkv;
    float* woc  = (float*)pwo;

    cudaFuncSetAttribute(gemm_qkv_kernel,
                         cudaFuncAttributeMaxDynamicSharedMemorySize, 73728);
    cudaFuncSetAttribute(gemm_o_kernel,
                         cudaFuncAttributeMaxDynamicSharedMemorySize, 73728);
    cudaFuncSetAttribute(attn_kernel,
                         cudaFuncAttributeMaxDynamicSharedMemorySize, 69632);

    // pre-convert inputs to tf32 (RNA)
    cvt_x_kernel<<<8192, 256>>>(x, xc);
    cvt_w_kernel<<<dim3(1024, 4), 256>>>(Wq, Wk, Wv, Wo, wqkv, woc);

    gemm_qkv_kernel<<<dim3(24, 64), 256, 73728>>>(xc, wqkv, bq, bk, bv, qb, kb, vb);
    attn_kernel<<<dim3(16, 64), 128, 69632>>>(qb, kb, vb, ab);
    gemm_o_kernel<<<dim3(8, 64), 256, 73728>>>(ab, woc, bo, out);
}